// round 4
// baseline (speedup 1.0000x reference)
#include <cuda_runtime.h>
#include <cuda_bf16.h>
#include <math.h>

// Problem constants
#define B_SZ 4
#define SEQ  2048
#define DM   1024
#define NH   16
#define DH   64
#define NTOK (B_SZ * SEQ)   // 8192

// ---------------------------------------------------------------------------
// Scratch (device globals; no allocation allowed)
// ---------------------------------------------------------------------------
__device__ float g_Q[(size_t)B_SZ * NH * SEQ * DH];   // [B,H,S,Dh]
__device__ float g_K[(size_t)B_SZ * NH * SEQ * DH];
__device__ float g_V[(size_t)B_SZ * NH * SEQ * DH];
__device__ float g_ctx[(size_t)NTOK * DM];            // [B*S, D]

// ---------------------------------------------------------------------------
// GEMM: out[M,N] = A[M,K] @ W[K,N] + bias
// BM=128, BN=64, BK=16, 256 threads, 8x4 per-thread tile.
// remap==1: scatter output into [B,H,S,Dh] layout (N-tile == one head).
// ---------------------------------------------------------------------------
#define BM 128
#define BN 64
#define BK 16

__global__ __launch_bounds__(256) void gemm_kernel(
    const float* __restrict__ A, const float* __restrict__ W,
    const float* __restrict__ bias, float* __restrict__ out, int remap)
{
    __shared__ float As[BK][BM];
    __shared__ float Bs[BK][BN];

    const int tid = threadIdx.x;
    const int tx = tid & 15;        // 0..15 -> N
    const int ty = tid >> 4;        // 0..15 -> M
    const int m0 = blockIdx.y * BM;
    const int n0 = blockIdx.x * BN;

    float acc[8][4];
#pragma unroll
    for (int r = 0; r < 8; ++r)
#pragma unroll
        for (int c = 0; c < 4; ++c) acc[r][c] = 0.f;

    const int arow = tid >> 2;            // 0..63
    const int ac4  = (tid & 3) * 4;       // 0,4,8,12
    const int brow = tid >> 4;            // 0..15
    const int bc4  = (tid & 15) * 4;      // 0..60

    for (int k0 = 0; k0 < DM; k0 += BK) {
        // Load A tile (transposed into As[k][m])
#pragma unroll
        for (int h = 0; h < 2; ++h) {
            int r = arow + h * 64;
            float4 av = *(const float4*)&A[(size_t)(m0 + r) * DM + k0 + ac4];
            As[ac4 + 0][r] = av.x;
            As[ac4 + 1][r] = av.y;
            As[ac4 + 2][r] = av.z;
            As[ac4 + 3][r] = av.w;
        }
        // Load B tile
        *(float4*)&Bs[brow][bc4] =
            *(const float4*)&W[(size_t)(k0 + brow) * DM + n0 + bc4];
        __syncthreads();

#pragma unroll
        for (int k = 0; k < BK; ++k) {
            float4 a0 = *(const float4*)&As[k][ty * 8];
            float4 a1 = *(const float4*)&As[k][ty * 8 + 4];
            float4 bv = *(const float4*)&Bs[k][tx * 4];
            float ar[8] = {a0.x, a0.y, a0.z, a0.w, a1.x, a1.y, a1.z, a1.w};
            float br[4] = {bv.x, bv.y, bv.z, bv.w};
#pragma unroll
            for (int r = 0; r < 8; ++r)
#pragma unroll
                for (int c = 0; c < 4; ++c) acc[r][c] += ar[r] * br[c];
        }
        __syncthreads();
    }

    // Epilogue
    float4 bvv = *(const float4*)&bias[n0 + tx * 4];
#pragma unroll
    for (int r = 0; r < 8; ++r) {
        float4 o;
        o.x = acc[r][0] + bvv.x;
        o.y = acc[r][1] + bvv.y;
        o.z = acc[r][2] + bvv.z;
        o.w = acc[r][3] + bvv.w;
        int t = m0 + ty * 8 + r;          // token id
        int col = n0 + tx * 4;
        if (remap) {
            int b  = t >> 11;             // /SEQ
            int s  = t & (SEQ - 1);
            int hh = col >> 6;            // /DH
            int dh = col & (DH - 1);
            *(float4*)&out[(((size_t)(b * NH + hh) * SEQ + s) * DH) + dh] = o;
        } else {
            *(float4*)&out[(size_t)t * DM + col] = o;
        }
    }
}

// ---------------------------------------------------------------------------
// Flash attention: one CTA per (b, h, 64-row q-tile). Online softmax.
// Smem: Qs[64][64], Kt[64][64] (d-major, XOR-swizzled), Vs[64][64], Ps[64][64].
// 256 threads as (tx 0..15 -> 4 cols, ty 0..15 -> 4 rows).
//
// Kt swizzle: logical (d, j) stored at
//   d*64 + ((j>>2) ^ (d & 15))*4 + (j & 3)
// - 16B aligned (float4-group granularity)
// - reads (lane tx reads logical j-group tx at row d -> phys group tx^(d&15)):
//   16 distinct groups across lanes -> conflict-free LDS.128
// - writes (lanes vary j, fixed d): banks ((j>>2)^(d&15))*4 + (j&3) cover all
//   32 banks -> conflict-free STS.32
// ---------------------------------------------------------------------------
#define FLASH_SMEM (4 * 64 * 64 * 4)

__device__ __forceinline__ int kt_phys(int d, int j) {
    return d * 64 + (((j >> 2) ^ (d & 15)) << 2) + (j & 3);
}

__global__ __launch_bounds__(256) void flash_kernel(
    const float* __restrict__ Q, const float* __restrict__ K,
    const float* __restrict__ V, float* __restrict__ ctx)
{
    extern __shared__ float sm[];
    float* Qs = sm;                       // [64][64]
    float* Kt = sm + 64 * 64;             // [64][64] swizzled, d-major
    float* Vs = Kt + 64 * 64;             // [64][64] row-major
    float* Ps = Vs + 64 * 64;             // [64][64]

    const int tid = threadIdx.x;
    const int tx = tid & 15;
    const int ty = tid >> 4;
    const int qt = blockIdx.x;
    const int h  = blockIdx.y;
    const int b  = blockIdx.z;

    const size_t head_off = (size_t)(b * NH + h) * SEQ * DH;
    const float* Qg = Q + head_off + (size_t)qt * 64 * DH;
    const float* Kg = K + head_off;
    const float* Vg = V + head_off;

    // Load Q tile, pre-scaled by 1/sqrt(Dh)
    for (int it = tid; it < 64 * 16; it += 256) {
        int r = it >> 4, c4 = (it & 15) * 4;
        float4 v = *(const float4*)&Qg[r * DH + c4];
        v.x *= 0.125f; v.y *= 0.125f; v.z *= 0.125f; v.w *= 0.125f;
        *(float4*)&Qs[r * 64 + c4] = v;
    }

    const int i0 = ty * 4;     // q rows
    const int j0 = tx * 4;     // k cols (score tile)
    const int dh0 = tx * 4;    // output head-dim cols

    float m[4], l[4], o[4][4];
#pragma unroll
    for (int r = 0; r < 4; ++r) {
        m[r] = -1e30f; l[r] = 0.f;
#pragma unroll
        for (int c = 0; c < 4; ++c) o[r][c] = 0.f;
    }

    for (int kt = 0; kt < SEQ / 64; ++kt) {
        __syncthreads();   // previous PV reads done before overwriting Kt/Vs

        // V tile: row-major copy (lanes vary d -> contiguous, conflict-free)
        for (int it = tid; it < 64 * 16; it += 256) {
            int r = it >> 4, c4 = (it & 15) * 4;
            *(float4*)&Vs[r * 64 + c4] =
                *(const float4*)&Vg[(size_t)(kt * 64 + r) * DH + c4];
        }
        // K tile: transposed + swizzled copy (lanes vary j -> conflict-free STS)
        for (int it = tid; it < 64 * 16; it += 256) {
            int j  = it & 63;             // k-row in tile
            int c4 = (it >> 6) * 4;       // d base
            float4 kv = *(const float4*)&Kg[(size_t)(kt * 64 + j) * DH + c4];
            Kt[kt_phys(c4 + 0, j)] = kv.x;
            Kt[kt_phys(c4 + 1, j)] = kv.y;
            Kt[kt_phys(c4 + 2, j)] = kv.z;
            Kt[kt_phys(c4 + 3, j)] = kv.w;
        }
        __syncthreads();

        // S = Qs @ K^T  (s[r][c] for rows i0+r, cols j0+c)
        float s[4][4];
#pragma unroll
        for (int r = 0; r < 4; ++r)
#pragma unroll
            for (int c = 0; c < 4; ++c) s[r][c] = 0.f;

#pragma unroll
        for (int d4 = 0; d4 < 16; ++d4) {
            float4 q[4];
#pragma unroll
            for (int r = 0; r < 4; ++r)
                q[r] = *(const float4*)&Qs[(i0 + r) * 64 + d4 * 4];

#define QK_U(COMP, OFF)                                                    \
            {                                                              \
                int d = d4 * 4 + OFF;                                      \
                float4 kv = *(const float4*)                               \
                    &Kt[d * 64 + ((tx ^ (d & 15)) << 2)];                  \
                _Pragma("unroll")                                          \
                for (int r = 0; r < 4; ++r) {                              \
                    s[r][0] += q[r].COMP * kv.x;                           \
                    s[r][1] += q[r].COMP * kv.y;                           \
                    s[r][2] += q[r].COMP * kv.z;                           \
                    s[r][3] += q[r].COMP * kv.w;                           \
                }                                                          \
            }
            QK_U(x, 0) QK_U(y, 1) QK_U(z, 2) QK_U(w, 3)
#undef QK_U
        }

        // Online softmax per row (row spread over the 16 tx lanes)
#pragma unroll
        for (int r = 0; r < 4; ++r) {
            float mx = fmaxf(fmaxf(s[r][0], s[r][1]), fmaxf(s[r][2], s[r][3]));
#pragma unroll
            for (int off = 8; off > 0; off >>= 1)
                mx = fmaxf(mx, __shfl_xor_sync(0xffffffffu, mx, off, 16));
            float mn = fmaxf(m[r], mx);
            float corr = __expf(m[r] - mn);
            m[r] = mn;
            float rs = 0.f;
#pragma unroll
            for (int c = 0; c < 4; ++c) {
                float p = __expf(s[r][c] - mn);
                s[r][c] = p;
                rs += p;
            }
#pragma unroll
            for (int off = 8; off > 0; off >>= 1)
                rs += __shfl_xor_sync(0xffffffffu, rs, off, 16);
            l[r] = l[r] * corr + rs;
#pragma unroll
            for (int c = 0; c < 4; ++c) o[r][c] *= corr;
            *(float4*)&Ps[(i0 + r) * 64 + j0] =
                make_float4(s[r][0], s[r][1], s[r][2], s[r][3]);
        }
        __syncthreads();   // Ps visible to all

        // O += P @ V
#pragma unroll
        for (int j4 = 0; j4 < 16; ++j4) {
            float4 p[4];
#pragma unroll
            for (int r = 0; r < 4; ++r)
                p[r] = *(const float4*)&Ps[(i0 + r) * 64 + j4 * 4];

#define PV_U(COMP, OFF)                                                   \
            {                                                             \
                float4 vv = *(const float4*)&Vs[(j4 * 4 + OFF) * 64 + dh0];\
                _Pragma("unroll")                                         \
                for (int r = 0; r < 4; ++r) {                             \
                    o[r][0] += p[r].COMP * vv.x;                          \
                    o[r][1] += p[r].COMP * vv.y;                          \
                    o[r][2] += p[r].COMP * vv.z;                          \
                    o[r][3] += p[r].COMP * vv.w;                          \
                }                                                         \
            }
            PV_U(x, 0) PV_U(y, 1) PV_U(z, 2) PV_U(w, 3)
#undef PV_U
        }
    }

    // Epilogue: normalize and write ctx in [B*S, D] layout
#pragma unroll
    for (int r = 0; r < 4; ++r) {
        float inv = 1.f / l[r];
        float4 ov = make_float4(o[r][0] * inv, o[r][1] * inv,
                                o[r][2] * inv, o[r][3] * inv);
        int srow = qt * 64 + i0 + r;
        *(float4*)&g_ctx[((size_t)(b * SEQ + srow)) * DM + h * DH + dh0] = ov;
        (void)ctx;
    }
}

// ---------------------------------------------------------------------------
// Launch
// ---------------------------------------------------------------------------
extern "C" void kernel_launch(void* const* d_in, const int* in_sizes, int n_in,
                              void* d_out, int out_size)
{
    const float* x  = (const float*)d_in[0];
    const float* Wq = (const float*)d_in[1];
    const float* bq = (const float*)d_in[2];
    const float* Wk = (const float*)d_in[3];
    const float* bk = (const float*)d_in[4];
    const float* Wv = (const float*)d_in[5];
    const float* bv = (const float*)d_in[6];
    const float* Wo = (const float*)d_in[7];
    const float* bo = (const float*)d_in[8];
    float* out = (float*)d_out;

    // Resolve scratch addresses
    float *Qp, *Kp, *Vp, *Cp;
    cudaGetSymbolAddress((void**)&Qp, g_Q);
    cudaGetSymbolAddress((void**)&Kp, g_K);
    cudaGetSymbolAddress((void**)&Vp, g_V);
    cudaGetSymbolAddress((void**)&Cp, g_ctx);

    cudaFuncSetAttribute(flash_kernel,
                         cudaFuncAttributeMaxDynamicSharedMemorySize, FLASH_SMEM);

    dim3 gg(DM / BN, NTOK / BM);   // (16, 64)
    gemm_kernel<<<gg, 256>>>(x, Wq, bq, Qp, 1);
    gemm_kernel<<<gg, 256>>>(x, Wk, bk, Kp, 1);
    gemm_kernel<<<gg, 256>>>(x, Wv, bv, Vp, 1);

    flash_kernel<<<dim3(SEQ / 64, NH, B_SZ), 256, FLASH_SMEM>>>(Qp, Kp, Vp, Cp);

    gemm_kernel<<<gg, 256>>>(Cp, Wo, bo, out, 0);
}

// round 8
// speedup vs baseline: 1.4505x; 1.4505x over previous
#include <cuda_runtime.h>
#include <cuda_bf16.h>
#include <math.h>
#include <stdint.h>

// Problem constants
#define B_SZ 4
#define SEQ  2048
#define DM   1024
#define NH   16
#define DH   64
#define NTOK (B_SZ * SEQ)   // 8192

// ---------------------------------------------------------------------------
// Scratch (device globals; no allocation allowed)
// ---------------------------------------------------------------------------
__device__ float g_Q[(size_t)B_SZ * NH * SEQ * DH];   // [B,H,S,Dh]
__device__ float g_K[(size_t)B_SZ * NH * SEQ * DH];
__device__ float g_V[(size_t)B_SZ * NH * SEQ * DH];
__device__ float g_ctx[(size_t)NTOK * DM];            // [B*S, D]

__device__ __forceinline__ uint32_t rn_tf32(float x) {
    uint32_t r;
    asm("cvt.rna.tf32.f32 %0, %1;" : "=r"(r) : "f"(x));
    return r;
}

// ---------------------------------------------------------------------------
// TF32 mma.sync GEMM: out[M,N] = A[M,K] @ W[K,N] + bias, K = DM = 1024.
// (Baseline PTX mma — the harness compiles PTX at target sm_103 (no 'a'),
//  which rejects all tcgen05.* instructions.)
//
// CTA: 256 thr = 2(M) x 4(N) warps; tile 128x128; per-warp 64x32 = 4x4 mma
// tiles of m16n8k8. BK=32 smem chunks.
//   As[128][36]: frag LDS bank = (4g + tig) & 31  -> conflict-free
//   Bs[32][136]: frag LDS bank = (8tig + g) & 31  -> conflict-free
// ---------------------------------------------------------------------------
__global__ __launch_bounds__(256) void mma_gemm(
    const float* __restrict__ A, const float* __restrict__ W,
    const float* __restrict__ bias, float* __restrict__ out, int remap)
{
    __shared__ uint32_t As[128][36];
    __shared__ uint32_t Bs[32][136];

    const int tid  = threadIdx.x;
    const int warp = tid >> 5, lane = tid & 31;
    const int wm = warp >> 2;          // 0..1
    const int wn = warp & 3;           // 0..3
    const int g  = lane >> 2;          // 0..7
    const int tig = lane & 3;          // 0..3
    const int m0 = blockIdx.y * 128;
    const int n0 = blockIdx.x * 128;

    float acc[4][4][4];
#pragma unroll
    for (int mt = 0; mt < 4; ++mt)
#pragma unroll
        for (int nt = 0; nt < 4; ++nt)
#pragma unroll
            for (int r = 0; r < 4; ++r) acc[mt][nt][r] = 0.f;

    for (int k0 = 0; k0 < DM; k0 += 32) {
        __syncthreads();
        // A tile: [128][32], coalesced float4 reads, tf32-rounded
#pragma unroll
        for (int i = 0; i < 4; ++i) {
            int it = i * 256 + tid;
            int r = it >> 3, c4 = it & 7;
            float4 v = *(const float4*)&A[(size_t)(m0 + r) * DM + k0 + c4 * 4];
            uint4 u = make_uint4(rn_tf32(v.x), rn_tf32(v.y),
                                 rn_tf32(v.z), rn_tf32(v.w));
            *(uint4*)&As[r][c4 * 4] = u;
        }
        // B tile: [32][128], coalesced float4 reads
#pragma unroll
        for (int i = 0; i < 4; ++i) {
            int it = i * 256 + tid;
            int k = it >> 5, n4 = it & 31;
            float4 v = *(const float4*)&W[(size_t)(k0 + k) * DM + n0 + n4 * 4];
            uint4 u = make_uint4(rn_tf32(v.x), rn_tf32(v.y),
                                 rn_tf32(v.z), rn_tf32(v.w));
            *(uint4*)&Bs[k][n4 * 4] = u;
        }
        __syncthreads();

#pragma unroll
        for (int kk = 0; kk < 32; kk += 8) {
            uint32_t a[4][4], b[4][2];
#pragma unroll
            for (int mt = 0; mt < 4; ++mt) {
                int row = wm * 64 + mt * 16;
                a[mt][0] = As[row + g    ][kk + tig];
                a[mt][1] = As[row + g + 8][kk + tig];
                a[mt][2] = As[row + g    ][kk + tig + 4];
                a[mt][3] = As[row + g + 8][kk + tig + 4];
            }
#pragma unroll
            for (int nt = 0; nt < 4; ++nt) {
                int coln = wn * 32 + nt * 8 + g;
                b[nt][0] = Bs[kk + tig    ][coln];
                b[nt][1] = Bs[kk + tig + 4][coln];
            }
#pragma unroll
            for (int mt = 0; mt < 4; ++mt)
#pragma unroll
                for (int nt = 0; nt < 4; ++nt) {
                    asm volatile(
                        "mma.sync.aligned.m16n8k8.row.col.f32.tf32.tf32.f32 "
                        "{%0,%1,%2,%3}, {%4,%5,%6,%7}, {%8,%9}, {%0,%1,%2,%3};"
                        : "+f"(acc[mt][nt][0]), "+f"(acc[mt][nt][1]),
                          "+f"(acc[mt][nt][2]), "+f"(acc[mt][nt][3])
                        : "r"(a[mt][0]), "r"(a[mt][1]),
                          "r"(a[mt][2]), "r"(a[mt][3]),
                          "r"(b[nt][0]), "r"(b[nt][1]));
                }
        }
    }

    // Epilogue. D frag: c0=(g,2t), c1=(g,2t+1), c2=(g+8,2t), c3=(g+8,2t+1)
#pragma unroll
    for (int mt = 0; mt < 4; ++mt) {
#pragma unroll
        for (int nt = 0; nt < 4; ++nt) {
            int col  = n0 + wn * 32 + nt * 8 + 2 * tig;
            float2 bv = *(const float2*)&bias[col];
#pragma unroll
            for (int hh = 0; hh < 2; ++hh) {
                int t = m0 + wm * 64 + mt * 16 + g + hh * 8;   // token
                float2 o = make_float2(acc[mt][nt][hh * 2 + 0] + bv.x,
                                       acc[mt][nt][hh * 2 + 1] + bv.y);
                if (remap) {
                    int bidx = t >> 11;
                    int srow = t & (SEQ - 1);
                    int head = col >> 6;
                    int dh   = col & (DH - 1);
                    *(float2*)&out[(((size_t)(bidx * NH + head) * SEQ + srow)
                                    * DH) + dh] = o;
                } else {
                    *(float2*)&out[(size_t)t * DM + col] = o;
                }
            }
        }
    }
}

// ---------------------------------------------------------------------------
// Flash attention (unchanged from passing R4): one CTA per (b,h,64-row qtile).
// ---------------------------------------------------------------------------
#define FLASH_SMEM (4 * 64 * 64 * 4)

__device__ __forceinline__ int kt_phys(int d, int j) {
    return d * 64 + (((j >> 2) ^ (d & 15)) << 2) + (j & 3);
}

__global__ __launch_bounds__(256) void flash_kernel(
    const float* __restrict__ Q, const float* __restrict__ K,
    const float* __restrict__ V, float* __restrict__ ctx)
{
    extern __shared__ float sm[];
    float* Qs = sm;                       // [64][64]
    float* Kt = sm + 64 * 64;             // [64][64] swizzled, d-major
    float* Vs = Kt + 64 * 64;             // [64][64] row-major
    float* Ps = Vs + 64 * 64;             // [64][64]

    const int tid = threadIdx.x;
    const int tx = tid & 15;
    const int ty = tid >> 4;
    const int qt = blockIdx.x;
    const int h  = blockIdx.y;
    const int b  = blockIdx.z;

    const size_t head_off = (size_t)(b * NH + h) * SEQ * DH;
    const float* Qg = Q + head_off + (size_t)qt * 64 * DH;
    const float* Kg = K + head_off;
    const float* Vg = V + head_off;

    for (int it = tid; it < 64 * 16; it += 256) {
        int r = it >> 4, c4 = (it & 15) * 4;
        float4 v = *(const float4*)&Qg[r * DH + c4];
        v.x *= 0.125f; v.y *= 0.125f; v.z *= 0.125f; v.w *= 0.125f;
        *(float4*)&Qs[r * 64 + c4] = v;
    }

    const int i0 = ty * 4;
    const int j0 = tx * 4;
    const int dh0 = tx * 4;

    float m[4], l[4], o[4][4];
#pragma unroll
    for (int r = 0; r < 4; ++r) {
        m[r] = -1e30f; l[r] = 0.f;
#pragma unroll
        for (int c = 0; c < 4; ++c) o[r][c] = 0.f;
    }

    for (int kt = 0; kt < SEQ / 64; ++kt) {
        __syncthreads();
        for (int it = tid; it < 64 * 16; it += 256) {
            int r = it >> 4, c4 = (it & 15) * 4;
            *(float4*)&Vs[r * 64 + c4] =
                *(const float4*)&Vg[(size_t)(kt * 64 + r) * DH + c4];
        }
        for (int it = tid; it < 64 * 16; it += 256) {
            int j  = it & 63;
            int c4 = (it >> 6) * 4;
            float4 kv = *(const float4*)&Kg[(size_t)(kt * 64 + j) * DH + c4];
            Kt[kt_phys(c4 + 0, j)] = kv.x;
            Kt[kt_phys(c4 + 1, j)] = kv.y;
            Kt[kt_phys(c4 + 2, j)] = kv.z;
            Kt[kt_phys(c4 + 3, j)] = kv.w;
        }
        __syncthreads();

        float s[4][4];
#pragma unroll
        for (int r = 0; r < 4; ++r)
#pragma unroll
            for (int c = 0; c < 4; ++c) s[r][c] = 0.f;

#pragma unroll
        for (int d4 = 0; d4 < 16; ++d4) {
            float4 q[4];
#pragma unroll
            for (int r = 0; r < 4; ++r)
                q[r] = *(const float4*)&Qs[(i0 + r) * 64 + d4 * 4];

#define QK_U(COMP, OFF)                                                    \
            {                                                              \
                int d = d4 * 4 + OFF;                                      \
                float4 kv = *(const float4*)                               \
                    &Kt[d * 64 + ((tx ^ (d & 15)) << 2)];                  \
                _Pragma("unroll")                                          \
                for (int r = 0; r < 4; ++r) {                              \
                    s[r][0] += q[r].COMP * kv.x;                           \
                    s[r][1] += q[r].COMP * kv.y;                           \
                    s[r][2] += q[r].COMP * kv.z;                           \
                    s[r][3] += q[r].COMP * kv.w;                           \
                }                                                          \
            }
            QK_U(x, 0) QK_U(y, 1) QK_U(z, 2) QK_U(w, 3)
#undef QK_U
        }

#pragma unroll
        for (int r = 0; r < 4; ++r) {
            float mx = fmaxf(fmaxf(s[r][0], s[r][1]), fmaxf(s[r][2], s[r][3]));
#pragma unroll
            for (int off = 8; off > 0; off >>= 1)
                mx = fmaxf(mx, __shfl_xor_sync(0xffffffffu, mx, off, 16));
            float mn = fmaxf(m[r], mx);
            float corr = __expf(m[r] - mn);
            m[r] = mn;
            float rs = 0.f;
#pragma unroll
            for (int c = 0; c < 4; ++c) {
                float p = __expf(s[r][c] - mn);
                s[r][c] = p;
                rs += p;
            }
#pragma unroll
            for (int off = 8; off > 0; off >>= 1)
                rs += __shfl_xor_sync(0xffffffffu, rs, off, 16);
            l[r] = l[r] * corr + rs;
#pragma unroll
            for (int c = 0; c < 4; ++c) o[r][c] *= corr;
            *(float4*)&Ps[(i0 + r) * 64 + j0] =
                make_float4(s[r][0], s[r][1], s[r][2], s[r][3]);
        }
        __syncthreads();

#pragma unroll
        for (int j4 = 0; j4 < 16; ++j4) {
            float4 p[4];
#pragma unroll
            for (int r = 0; r < 4; ++r)
                p[r] = *(const float4*)&Ps[(i0 + r) * 64 + j4 * 4];

#define PV_U(COMP, OFF)                                                   \
            {                                                             \
                float4 vv = *(const float4*)&Vs[(j4 * 4 + OFF) * 64 + dh0];\
                _Pragma("unroll")                                         \
                for (int r = 0; r < 4; ++r) {                             \
                    o[r][0] += p[r].COMP * vv.x;                          \
                    o[r][1] += p[r].COMP * vv.y;                          \
                    o[r][2] += p[r].COMP * vv.z;                          \
                    o[r][3] += p[r].COMP * vv.w;                          \
                }                                                         \
            }
            PV_U(x, 0) PV_U(y, 1) PV_U(z, 2) PV_U(w, 3)
#undef PV_U
        }
    }

#pragma unroll
    for (int r = 0; r < 4; ++r) {
        float inv = 1.f / l[r];
        float4 ov = make_float4(o[r][0] * inv, o[r][1] * inv,
                                o[r][2] * inv, o[r][3] * inv);
        int srow = qt * 64 + i0 + r;
        *(float4*)&g_ctx[((size_t)(b * SEQ + srow)) * DM + h * DH + dh0] = ov;
        (void)ctx;
    }
}

// ---------------------------------------------------------------------------
// Launch
// ---------------------------------------------------------------------------
extern "C" void kernel_launch(void* const* d_in, const int* in_sizes, int n_in,
                              void* d_out, int out_size)
{
    const float* x  = (const float*)d_in[0];
    const float* Wq = (const float*)d_in[1];
    const float* bq = (const float*)d_in[2];
    const float* Wk = (const float*)d_in[3];
    const float* bk = (const float*)d_in[4];
    const float* Wv = (const float*)d_in[5];
    const float* bv = (const float*)d_in[6];
    const float* Wo = (const float*)d_in[7];
    const float* bo = (const float*)d_in[8];
    float* out = (float*)d_out;

    float *Qp, *Kp, *Vp, *Cp;
    cudaGetSymbolAddress((void**)&Qp, g_Q);
    cudaGetSymbolAddress((void**)&Kp, g_K);
    cudaGetSymbolAddress((void**)&Vp, g_V);
    cudaGetSymbolAddress((void**)&Cp, g_ctx);

    cudaFuncSetAttribute(flash_kernel,
                         cudaFuncAttributeMaxDynamicSharedMemorySize, FLASH_SMEM);

    dim3 gg(DM / 128, NTOK / 128);   // (8, 64)
    mma_gemm<<<gg, 256>>>(x, Wq, bq, Qp, 1);
    mma_gemm<<<gg, 256>>>(x, Wk, bk, Kp, 1);
    mma_gemm<<<gg, 256>>>(x, Wv, bv, Vp, 1);

    flash_kernel<<<dim3(SEQ / 64, NH, B_SZ), 256, FLASH_SMEM>>>(Qp, Kp, Vp, Cp);

    mma_gemm<<<gg, 256>>>(Cp, Wo, bo, out, 0);
}

// round 10
// speedup vs baseline: 1.9434x; 1.3398x over previous
#include <cuda_runtime.h>
#include <cuda_bf16.h>
#include <math.h>
#include <stdint.h>

// Problem constants
#define B_SZ 4
#define SEQ  2048
#define DM   1024
#define NH   16
#define DH   64
#define NTOK (B_SZ * SEQ)   // 8192

// ---------------------------------------------------------------------------
// Scratch (device globals; no allocation allowed)
// ---------------------------------------------------------------------------
__device__ float g_Q[(size_t)B_SZ * NH * SEQ * DH];   // [B,H,S,Dh]
__device__ float g_K[(size_t)B_SZ * NH * SEQ * DH];
__device__ float g_V[(size_t)B_SZ * NH * SEQ * DH];
__device__ float g_ctx[(size_t)NTOK * DM];            // [B*S, D]

__device__ __forceinline__ uint32_t rn_tf32(float x) {
    uint32_t r;
    asm("cvt.rna.tf32.f32 %0, %1;" : "=r"(r) : "f"(x));
    return r;
}

__device__ __forceinline__ void mma_tf32(float* c, const uint32_t* a,
                                         uint32_t b0, uint32_t b1) {
    asm volatile(
        "mma.sync.aligned.m16n8k8.row.col.f32.tf32.tf32.f32 "
        "{%0,%1,%2,%3}, {%4,%5,%6,%7}, {%8,%9}, {%0,%1,%2,%3};"
        : "+f"(c[0]), "+f"(c[1]), "+f"(c[2]), "+f"(c[3])
        : "r"(a[0]), "r"(a[1]), "r"(a[2]), "r"(a[3]), "r"(b0), "r"(b1));
}

// ---------------------------------------------------------------------------
// TF32 mma.sync GEMM (unchanged from passing R8).
// ---------------------------------------------------------------------------
__global__ __launch_bounds__(256) void mma_gemm(
    const float* __restrict__ A, const float* __restrict__ W,
    const float* __restrict__ bias, float* __restrict__ out, int remap)
{
    __shared__ uint32_t As[128][36];
    __shared__ uint32_t Bs[32][136];

    const int tid  = threadIdx.x;
    const int warp = tid >> 5, lane = tid & 31;
    const int wm = warp >> 2;
    const int wn = warp & 3;
    const int g  = lane >> 2;
    const int tig = lane & 3;
    const int m0 = blockIdx.y * 128;
    const int n0 = blockIdx.x * 128;

    float acc[4][4][4];
#pragma unroll
    for (int mt = 0; mt < 4; ++mt)
#pragma unroll
        for (int nt = 0; nt < 4; ++nt)
#pragma unroll
            for (int r = 0; r < 4; ++r) acc[mt][nt][r] = 0.f;

    for (int k0 = 0; k0 < DM; k0 += 32) {
        __syncthreads();
#pragma unroll
        for (int i = 0; i < 4; ++i) {
            int it = i * 256 + tid;
            int r = it >> 3, c4 = it & 7;
            float4 v = *(const float4*)&A[(size_t)(m0 + r) * DM + k0 + c4 * 4];
            uint4 u = make_uint4(rn_tf32(v.x), rn_tf32(v.y),
                                 rn_tf32(v.z), rn_tf32(v.w));
            *(uint4*)&As[r][c4 * 4] = u;
        }
#pragma unroll
        for (int i = 0; i < 4; ++i) {
            int it = i * 256 + tid;
            int k = it >> 5, n4 = it & 31;
            float4 v = *(const float4*)&W[(size_t)(k0 + k) * DM + n0 + n4 * 4];
            uint4 u = make_uint4(rn_tf32(v.x), rn_tf32(v.y),
                                 rn_tf32(v.z), rn_tf32(v.w));
            *(uint4*)&Bs[k][n4 * 4] = u;
        }
        __syncthreads();

#pragma unroll
        for (int kk = 0; kk < 32; kk += 8) {
            uint32_t a[4][4], b[4][2];
#pragma unroll
            for (int mt = 0; mt < 4; ++mt) {
                int row = wm * 64 + mt * 16;
                a[mt][0] = As[row + g    ][kk + tig];
                a[mt][1] = As[row + g + 8][kk + tig];
                a[mt][2] = As[row + g    ][kk + tig + 4];
                a[mt][3] = As[row + g + 8][kk + tig + 4];
            }
#pragma unroll
            for (int nt = 0; nt < 4; ++nt) {
                int coln = wn * 32 + nt * 8 + g;
                b[nt][0] = Bs[kk + tig    ][coln];
                b[nt][1] = Bs[kk + tig + 4][coln];
            }
#pragma unroll
            for (int mt = 0; mt < 4; ++mt)
#pragma unroll
                for (int nt = 0; nt < 4; ++nt)
                    mma_tf32(acc[mt][nt], a[mt], b[nt][0], b[nt][1]);
        }
    }

#pragma unroll
    for (int mt = 0; mt < 4; ++mt) {
#pragma unroll
        for (int nt = 0; nt < 4; ++nt) {
            int col  = n0 + wn * 32 + nt * 8 + 2 * tig;
            float2 bv = *(const float2*)&bias[col];
#pragma unroll
            for (int hh = 0; hh < 2; ++hh) {
                int t = m0 + wm * 64 + mt * 16 + g + hh * 8;
                float2 o = make_float2(acc[mt][nt][hh * 2 + 0] + bv.x,
                                       acc[mt][nt][hh * 2 + 1] + bv.y);
                if (remap) {
                    int bidx = t >> 11;
                    int srow = t & (SEQ - 1);
                    int head = col >> 6;
                    int dh   = col & (DH - 1);
                    *(float2*)&out[(((size_t)(bidx * NH + head) * SEQ + srow)
                                    * DH) + dh] = o;
                } else {
                    *(float2*)&out[(size_t)t * DM + col] = o;
                }
            }
        }
    }
}

// ---------------------------------------------------------------------------
// TF32 mma flash attention.
// CTA = (b, h, 128-q-row tile); 8 warps x 16 q-rows; K-blocks of 64.
// Smem strides chosen for conflict-free fragment access:
//   Ks stride 68: QK B-frag bank = 4g+tig            (all 32 distinct)
//   Ps stride 76: PV A-frag bank = 12g+tig+c         (all 32 distinct)
//                 P float2 store banks cover 0..31 exactly once
//   Vs stride 72: PV B-frag bank = 8tig+g            (all 32 distinct)
// Q frags preloaded to registers; Qs region (stride 68) reused as Ps.
// ---------------------------------------------------------------------------
#define QS_STR 68
#define PS_STR 76
#define KS_STR 68
#define VS_STR 72
#define PS_U32 (128 * PS_STR)          // 9728 (>= Qs 128*68)
#define KS_U32 (64 * KS_STR)           // 4352
#define VS_U32 (64 * VS_STR)           // 4608
#define FLASH_SMEM ((PS_U32 + KS_U32 + VS_U32) * 4)   // 74752 B

__global__ __launch_bounds__(256, 2) void flash_mma(
    const float* __restrict__ Q, const float* __restrict__ K,
    const float* __restrict__ V)
{
    extern __shared__ uint32_t sm4[];
    uint32_t* Ps = sm4;                 // also Qs in prologue
    uint32_t* Ks = sm4 + PS_U32;
    uint32_t* Vs = Ks + KS_U32;

    const int tid  = threadIdx.x;
    const int warp = tid >> 5, lane = tid & 31;
    const int g    = lane >> 2;         // 0..7
    const int tig  = lane & 3;          // 0..3
    const int qt = blockIdx.x;
    const int h  = blockIdx.y;
    const int b  = blockIdx.z;

    const size_t head_off = (size_t)(b * NH + h) * SEQ * DH;
    const float* Qg = Q + head_off + (size_t)qt * 128 * DH;
    const float* Kg = K + head_off;
    const float* Vg = V + head_off;

    // --- Prologue: Q tile -> smem (scaled, tf32), then frags -> registers ---
    for (int it = tid; it < 128 * 16; it += 256) {
        int r = it >> 4, c4 = (it & 15) * 4;
        float4 v = *(const float4*)&Qg[r * DH + c4];
        uint4 u = make_uint4(rn_tf32(v.x * 0.125f), rn_tf32(v.y * 0.125f),
                             rn_tf32(v.z * 0.125f), rn_tf32(v.w * 0.125f));
        *(uint4*)&Ps[r * QS_STR + c4] = u;
    }
    __syncthreads();

    const int r0 = warp * 16 + g;       // this thread's first q-row (local)
    uint32_t qf[8][4];
#pragma unroll
    for (int kk = 0; kk < 8; ++kk) {
        qf[kk][0] = Ps[r0 * QS_STR + kk * 8 + tig];
        qf[kk][1] = Ps[(r0 + 8) * QS_STR + kk * 8 + tig];
        qf[kk][2] = Ps[r0 * QS_STR + kk * 8 + tig + 4];
        qf[kk][3] = Ps[(r0 + 8) * QS_STR + kk * 8 + tig + 4];
    }
    __syncthreads();    // all Q frags read before Ps region is reused

    float o[8][4];
#pragma unroll
    for (int nt = 0; nt < 8; ++nt)
#pragma unroll
        for (int r = 0; r < 4; ++r) o[nt][r] = 0.f;
    float m0 = -1e30f, m1 = -1e30f, l0 = 0.f, l1 = 0.f;

    for (int kb = 0; kb < SEQ / 64; ++kb) {
        // Load K/V tiles (tf32)
        for (int it = tid; it < 64 * 16; it += 256) {
            int r = it >> 4, c4 = (it & 15) * 4;
            float4 kv = *(const float4*)&Kg[(size_t)(kb * 64 + r) * DH + c4];
            *(uint4*)&Ks[r * KS_STR + c4] =
                make_uint4(rn_tf32(kv.x), rn_tf32(kv.y),
                           rn_tf32(kv.z), rn_tf32(kv.w));
            float4 vv = *(const float4*)&Vg[(size_t)(kb * 64 + r) * DH + c4];
            *(uint4*)&Vs[r * VS_STR + c4] =
                make_uint4(rn_tf32(vv.x), rn_tf32(vv.y),
                           rn_tf32(vv.z), rn_tf32(vv.w));
        }
        __syncthreads();

        // S = Q @ K^T for this warp's 16 rows x 64 cols
        float s[8][4];
#pragma unroll
        for (int nt = 0; nt < 8; ++nt)
#pragma unroll
            for (int r = 0; r < 4; ++r) s[nt][r] = 0.f;
#pragma unroll
        for (int kk = 0; kk < 8; ++kk) {
#pragma unroll
            for (int nt = 0; nt < 8; ++nt) {
                uint32_t b0 = Ks[(nt * 8 + g) * KS_STR + kk * 8 + tig];
                uint32_t b1 = Ks[(nt * 8 + g) * KS_STR + kk * 8 + tig + 4];
                mma_tf32(s[nt], qf[kk], b0, b1);
            }
        }

        // Online softmax (rows r0 and r0+8; reduce over 4-lane tig group)
        float mx0 = -1e30f, mx1 = -1e30f;
#pragma unroll
        for (int nt = 0; nt < 8; ++nt) {
            mx0 = fmaxf(mx0, fmaxf(s[nt][0], s[nt][1]));
            mx1 = fmaxf(mx1, fmaxf(s[nt][2], s[nt][3]));
        }
#pragma unroll
        for (int off = 1; off < 4; off <<= 1) {
            mx0 = fmaxf(mx0, __shfl_xor_sync(0xffffffffu, mx0, off, 4));
            mx1 = fmaxf(mx1, __shfl_xor_sync(0xffffffffu, mx1, off, 4));
        }
        float mn0 = fmaxf(m0, mx0), mn1 = fmaxf(m1, mx1);
        float c0 = __expf(m0 - mn0), c1 = __expf(m1 - mn1);
        m0 = mn0; m1 = mn1;

        float sum0 = 0.f, sum1 = 0.f;
#pragma unroll
        for (int nt = 0; nt < 8; ++nt) {
            s[nt][0] = __expf(s[nt][0] - mn0);
            s[nt][1] = __expf(s[nt][1] - mn0);
            s[nt][2] = __expf(s[nt][2] - mn1);
            s[nt][3] = __expf(s[nt][3] - mn1);
            sum0 += s[nt][0] + s[nt][1];
            sum1 += s[nt][2] + s[nt][3];
        }
#pragma unroll
        for (int off = 1; off < 4; off <<= 1) {
            sum0 += __shfl_xor_sync(0xffffffffu, sum0, off, 4);
            sum1 += __shfl_xor_sync(0xffffffffu, sum1, off, 4);
        }
        l0 = l0 * c0 + sum0;
        l1 = l1 * c1 + sum1;
#pragma unroll
        for (int nt = 0; nt < 8; ++nt) {
            o[nt][0] *= c0; o[nt][1] *= c0;
            o[nt][2] *= c1; o[nt][3] *= c1;
            // Write P (tf32) for the PV mma
            *(uint2*)&Ps[r0 * PS_STR + nt * 8 + 2 * tig] =
                make_uint2(rn_tf32(s[nt][0]), rn_tf32(s[nt][1]));
            *(uint2*)&Ps[(r0 + 8) * PS_STR + nt * 8 + 2 * tig] =
                make_uint2(rn_tf32(s[nt][2]), rn_tf32(s[nt][3]));
        }
        __syncwarp();   // P rows are warp-private; warp-level visibility is enough

        // O += P @ V
#pragma unroll
        for (int kk = 0; kk < 8; ++kk) {
            uint32_t a[4];
            a[0] = Ps[r0 * PS_STR + kk * 8 + tig];
            a[1] = Ps[(r0 + 8) * PS_STR + kk * 8 + tig];
            a[2] = Ps[r0 * PS_STR + kk * 8 + tig + 4];
            a[3] = Ps[(r0 + 8) * PS_STR + kk * 8 + tig + 4];
#pragma unroll
            for (int nt = 0; nt < 8; ++nt) {
                uint32_t b0 = Vs[(kk * 8 + tig) * VS_STR + nt * 8 + g];
                uint32_t b1 = Vs[(kk * 8 + tig + 4) * VS_STR + nt * 8 + g];
                mma_tf32(o[nt], a, b0, b1);
            }
        }
        __syncthreads();   // K/V/P fully consumed before next block overwrites
    }

    // Epilogue: normalize, write ctx [B*S, DM]
    const float inv0 = 1.f / l0, inv1 = 1.f / l1;
    const int row0 = qt * 128 + r0;
#pragma unroll
    for (int nt = 0; nt < 8; ++nt) {
        int col = h * DH + nt * 8 + 2 * tig;
        *(float2*)&g_ctx[(size_t)(b * SEQ + row0) * DM + col] =
            make_float2(o[nt][0] * inv0, o[nt][1] * inv0);
        *(float2*)&g_ctx[(size_t)(b * SEQ + row0 + 8) * DM + col] =
            make_float2(o[nt][2] * inv1, o[nt][3] * inv1);
    }
}

// ---------------------------------------------------------------------------
// Launch
// ---------------------------------------------------------------------------
extern "C" void kernel_launch(void* const* d_in, const int* in_sizes, int n_in,
                              void* d_out, int out_size)
{
    const float* x  = (const float*)d_in[0];
    const float* Wq = (const float*)d_in[1];
    const float* bq = (const float*)d_in[2];
    const float* Wk = (const float*)d_in[3];
    const float* bk = (const float*)d_in[4];
    const float* Wv = (const float*)d_in[5];
    const float* bv = (const float*)d_in[6];
    const float* Wo = (const float*)d_in[7];
    const float* bo = (const float*)d_in[8];
    float* out = (float*)d_out;

    float *Qp, *Kp, *Vp, *Cp;
    cudaGetSymbolAddress((void**)&Qp, g_Q);
    cudaGetSymbolAddress((void**)&Kp, g_K);
    cudaGetSymbolAddress((void**)&Vp, g_V);
    cudaGetSymbolAddress((void**)&Cp, g_ctx);

    cudaFuncSetAttribute(flash_mma,
                         cudaFuncAttributeMaxDynamicSharedMemorySize, FLASH_SMEM);

    dim3 gg(DM / 128, NTOK / 128);   // (8, 64)
    mma_gemm<<<gg, 256>>>(x, Wq, bq, Qp, 1);
    mma_gemm<<<gg, 256>>>(x, Wk, bk, Kp, 1);
    mma_gemm<<<gg, 256>>>(x, Wv, bv, Vp, 1);

    flash_mma<<<dim3(SEQ / 128, NH, B_SZ), 256, FLASH_SMEM>>>(Qp, Kp, Vp);

    mma_gemm<<<gg, 256>>>(Cp, Wo, bo, out, 0);
}

// round 11
// speedup vs baseline: 3.3555x; 1.7266x over previous
#include <cuda_runtime.h>
#include <cuda_bf16.h>
#include <math.h>
#include <stdint.h>

// Problem constants
#define B_SZ 4
#define SEQ  2048
#define DM   1024
#define NH   16
#define DH   64
#define NTOK (B_SZ * SEQ)   // 8192

// ---------------------------------------------------------------------------
// Scratch (device globals).
// g_Q/g_K: uint32 tf32 bits, [B,H,S, p8(dh)]   (Q pre-scaled by 0.125)
// g_V:     uint32 tf32 bits, [B,H, S/64, dh, p8(s%64)]  (transposed per block)
// g_ctx:   plain fp32 [B*S, DM]
// p8 pairs (t, t+4) adjacently within each 8-group: p8 = base + 2*(k&3) + (k>>2)&1
// ---------------------------------------------------------------------------
__device__ uint32_t g_Q[(size_t)B_SZ * NH * SEQ * DH];
__device__ uint32_t g_K[(size_t)B_SZ * NH * SEQ * DH];
__device__ uint32_t g_V[(size_t)B_SZ * NH * SEQ * DH];
__device__ float    g_ctx[(size_t)NTOK * DM];

__device__ __forceinline__ int p8(int k) {
    return (k & ~7) + ((k & 3) << 1) + ((k >> 2) & 1);
}

__device__ __forceinline__ uint32_t rn_tf32(float x) {
    uint32_t r;
    asm("cvt.rna.tf32.f32 %0, %1;" : "=r"(r) : "f"(x));
    return r;
}

__device__ __forceinline__ void mma_tf32(float* c, const uint32_t* a,
                                         uint32_t b0, uint32_t b1) {
    asm volatile(
        "mma.sync.aligned.m16n8k8.row.col.f32.tf32.tf32.f32 "
        "{%0,%1,%2,%3}, {%4,%5,%6,%7}, {%8,%9}, {%0,%1,%2,%3};"
        : "+f"(c[0]), "+f"(c[1]), "+f"(c[2]), "+f"(c[3])
        : "r"(a[0]), "r"(a[1]), "r"(a[2]), "r"(a[3]), "r"(b0), "r"(b1));
}

// ---------------------------------------------------------------------------
// TF32 mma.sync GEMM (mainloop = validated R8/R10).
// mode 0: plain fp32 out [M, DM]
// mode 1: Q  -> tf32 bits, *0.125, [B,H,S,p8(dh)]
// mode 2: K  -> tf32 bits,          [B,H,S,p8(dh)]
// mode 3: V  -> tf32 bits, [B,H, s/64, dh, p8(s%64)]
// ---------------------------------------------------------------------------
__global__ __launch_bounds__(256) void mma_gemm(
    const float* __restrict__ A, const float* __restrict__ W,
    const float* __restrict__ bias, void* __restrict__ outv, int mode)
{
    __shared__ uint32_t As[128][36];
    __shared__ uint32_t Bs[32][136];

    const int tid  = threadIdx.x;
    const int warp = tid >> 5, lane = tid & 31;
    const int wm = warp >> 2;
    const int wn = warp & 3;
    const int g  = lane >> 2;
    const int tig = lane & 3;
    const int m0 = blockIdx.y * 128;
    const int n0 = blockIdx.x * 128;

    float acc[4][4][4];
#pragma unroll
    for (int mt = 0; mt < 4; ++mt)
#pragma unroll
        for (int nt = 0; nt < 4; ++nt)
#pragma unroll
            for (int r = 0; r < 4; ++r) acc[mt][nt][r] = 0.f;

    for (int k0 = 0; k0 < DM; k0 += 32) {
        __syncthreads();
#pragma unroll
        for (int i = 0; i < 4; ++i) {
            int it = i * 256 + tid;
            int r = it >> 3, c4 = it & 7;
            float4 v = *(const float4*)&A[(size_t)(m0 + r) * DM + k0 + c4 * 4];
            uint4 u = make_uint4(rn_tf32(v.x), rn_tf32(v.y),
                                 rn_tf32(v.z), rn_tf32(v.w));
            *(uint4*)&As[r][c4 * 4] = u;
        }
#pragma unroll
        for (int i = 0; i < 4; ++i) {
            int it = i * 256 + tid;
            int k = it >> 5, n4 = it & 31;
            float4 v = *(const float4*)&W[(size_t)(k0 + k) * DM + n0 + n4 * 4];
            uint4 u = make_uint4(rn_tf32(v.x), rn_tf32(v.y),
                                 rn_tf32(v.z), rn_tf32(v.w));
            *(uint4*)&Bs[k][n4 * 4] = u;
        }
        __syncthreads();

#pragma unroll
        for (int kk = 0; kk < 32; kk += 8) {
            uint32_t a[4][4], b[4][2];
#pragma unroll
            for (int mt = 0; mt < 4; ++mt) {
                int row = wm * 64 + mt * 16;
                a[mt][0] = As[row + g    ][kk + tig];
                a[mt][1] = As[row + g + 8][kk + tig];
                a[mt][2] = As[row + g    ][kk + tig + 4];
                a[mt][3] = As[row + g + 8][kk + tig + 4];
            }
#pragma unroll
            for (int nt = 0; nt < 4; ++nt) {
                int coln = wn * 32 + nt * 8 + g;
                b[nt][0] = Bs[kk + tig    ][coln];
                b[nt][1] = Bs[kk + tig + 4][coln];
            }
#pragma unroll
            for (int mt = 0; mt < 4; ++mt)
#pragma unroll
                for (int nt = 0; nt < 4; ++nt)
                    mma_tf32(acc[mt][nt], a[mt], b[nt][0], b[nt][1]);
        }
    }

#pragma unroll
    for (int mt = 0; mt < 4; ++mt) {
#pragma unroll
        for (int nt = 0; nt < 4; ++nt) {
            int col  = n0 + wn * 32 + nt * 8 + 2 * tig;
            float2 bv = *(const float2*)&bias[col];
#pragma unroll
            for (int hh = 0; hh < 2; ++hh) {
                int t = m0 + wm * 64 + mt * 16 + g + hh * 8;
                float ox = acc[mt][nt][hh * 2 + 0] + bv.x;
                float oy = acc[mt][nt][hh * 2 + 1] + bv.y;
                if (mode == 0) {
                    *(float2*)&((float*)outv)[(size_t)t * DM + col] =
                        make_float2(ox, oy);
                } else {
                    int bidx = t >> 11;
                    int srow = t & (SEQ - 1);
                    int head = col >> 6;
                    int dh   = col & (DH - 1);
                    uint32_t* dst = (uint32_t*)outv;
                    size_t hb = (size_t)(bidx * NH + head) * SEQ * DH;
                    if (mode != 3) {
                        float sc = (mode == 1) ? 0.125f : 1.0f;
                        dst[hb + (size_t)srow * DH + p8(dh)]     = rn_tf32(ox * sc);
                        dst[hb + (size_t)srow * DH + p8(dh + 1)] = rn_tf32(oy);
                        if (mode == 1)
                            dst[hb + (size_t)srow * DH + p8(dh + 1)] =
                                rn_tf32(oy * sc);
                    } else {
                        size_t base = hb + (size_t)(srow >> 6) * (DH * 64)
                                      + p8(srow & 63);
                        dst[base + (size_t)dh * 64]       = rn_tf32(ox);
                        dst[base + (size_t)(dh + 1) * 64] = rn_tf32(oy);
                    }
                }
            }
        }
    }
}

// ---------------------------------------------------------------------------
// TF32 mma flash attention, v2.
// CTA = 128 thr (4 warps) x 128 q-rows; each warp 32 rows (mt=2 m16 tiles).
// B-fragments (K and V) reused across both m-tiles -> LDS bytes ~halved.
// All K/V/Q loads are pre-permuted tf32 (pair (t,t+4) adjacent) -> LDS.64.
//   Ks/Vs stride 72: LDS.64 frag banks 8g+2tig -> each even residue twice.
//   Ps stride 76: A-frag banks 12g+tig -> all distinct (validated R10).
// Q fragments loaded directly from gmem (L2-resident).
// ---------------------------------------------------------------------------
#define KS_STR 72
#define VS_STR 72
#define PS_STR 76
#define PS_U32 (128 * PS_STR)          // 9728
#define KS_U32 (64 * KS_STR)           // 4608
#define VS_U32 (64 * VS_STR)           // 4608
#define FLASH_SMEM ((PS_U32 + KS_U32 + VS_U32) * 4)   // 75776 B

__global__ __launch_bounds__(128, 2) void flash_mma(
    const uint32_t* __restrict__ Q, const uint32_t* __restrict__ K,
    const uint32_t* __restrict__ V)
{
    extern __shared__ uint32_t sm4[];
    uint32_t* Ps = sm4;
    uint32_t* Ks = sm4 + PS_U32;
    uint32_t* Vs = Ks + KS_U32;

    const int tid  = threadIdx.x;
    const int warp = tid >> 5, lane = tid & 31;
    const int g    = lane >> 2;         // 0..7
    const int tig  = lane & 3;          // 0..3
    const int qt = blockIdx.x;
    const int h  = blockIdx.y;
    const int b  = blockIdx.z;

    const size_t head_off = (size_t)(b * NH + h) * SEQ * DH;
    const uint32_t* Qg = Q + head_off + (size_t)qt * 128 * DH;
    const uint32_t* Kg = K + head_off;
    const uint32_t* Vg = V + head_off;

    // Q fragments straight from gmem (paired layout -> LDG.64)
    uint32_t qf[2][8][4];
#pragma unroll
    for (int mt = 0; mt < 2; ++mt) {
        const int row = warp * 32 + mt * 16 + g;
#pragma unroll
        for (int kk = 0; kk < 8; ++kk) {
            uint2 q02 = *(const uint2*)&Qg[(size_t)row * DH + kk * 8 + 2 * tig];
            uint2 q13 = *(const uint2*)&Qg[(size_t)(row + 8) * DH + kk * 8 + 2 * tig];
            qf[mt][kk][0] = q02.x; qf[mt][kk][2] = q02.y;
            qf[mt][kk][1] = q13.x; qf[mt][kk][3] = q13.y;
        }
    }

    float o[2][8][4];
#pragma unroll
    for (int mt = 0; mt < 2; ++mt)
#pragma unroll
        for (int nt = 0; nt < 8; ++nt)
#pragma unroll
            for (int r = 0; r < 4; ++r) o[mt][nt][r] = 0.f;
    float m[2][2], l[2][2];
#pragma unroll
    for (int mt = 0; mt < 2; ++mt) {
        m[mt][0] = m[mt][1] = -1e30f;
        l[mt][0] = l[mt][1] = 0.f;
    }

    for (int kb = 0; kb < SEQ / 64; ++kb) {
        __syncthreads();   // prior kb's K/V reads complete
        // Tile loads: straight uint4 copies (pre-permuted tf32 in gmem)
#pragma unroll
        for (int i = 0; i < 8; ++i) {
            int it = i * 128 + tid;
            int r = it >> 4, c4 = (it & 15) * 4;
            *(uint4*)&Ks[r * KS_STR + c4] =
                *(const uint4*)&Kg[(size_t)(kb * 64 + r) * DH + c4];
            *(uint4*)&Vs[r * VS_STR + c4] =
                *(const uint4*)&Vg[(size_t)kb * (DH * 64) + r * 64 + c4];
        }
        __syncthreads();

        // S = Q @ K^T : 32 rows x 64 cols per warp, B-frags shared across mt
        float s[2][8][4];
#pragma unroll
        for (int mt = 0; mt < 2; ++mt)
#pragma unroll
            for (int nt = 0; nt < 8; ++nt)
#pragma unroll
                for (int r = 0; r < 4; ++r) s[mt][nt][r] = 0.f;
#pragma unroll
        for (int kk = 0; kk < 8; ++kk) {
#pragma unroll
            for (int nt = 0; nt < 8; ++nt) {
                uint2 bb = *(const uint2*)
                    &Ks[(nt * 8 + g) * KS_STR + kk * 8 + 2 * tig];
                mma_tf32(s[0][nt], qf[0][kk], bb.x, bb.y);
                mma_tf32(s[1][nt], qf[1][kk], bb.x, bb.y);
            }
        }

        // Online softmax per m-tile (rows g and g+8; reduce over 4-lane quad)
#pragma unroll
        for (int mt = 0; mt < 2; ++mt) {
            float mx0 = -1e30f, mx1 = -1e30f;
#pragma unroll
            for (int nt = 0; nt < 8; ++nt) {
                mx0 = fmaxf(mx0, fmaxf(s[mt][nt][0], s[mt][nt][1]));
                mx1 = fmaxf(mx1, fmaxf(s[mt][nt][2], s[mt][nt][3]));
            }
#pragma unroll
            for (int off = 1; off < 4; off <<= 1) {
                mx0 = fmaxf(mx0, __shfl_xor_sync(0xffffffffu, mx0, off, 4));
                mx1 = fmaxf(mx1, __shfl_xor_sync(0xffffffffu, mx1, off, 4));
            }
            float mn0 = fmaxf(m[mt][0], mx0), mn1 = fmaxf(m[mt][1], mx1);
            float c0 = __expf(m[mt][0] - mn0), c1 = __expf(m[mt][1] - mn1);
            m[mt][0] = mn0; m[mt][1] = mn1;

            float sum0 = 0.f, sum1 = 0.f;
            const int row = warp * 32 + mt * 16 + g;
#pragma unroll
            for (int nt = 0; nt < 8; ++nt) {
                s[mt][nt][0] = __expf(s[mt][nt][0] - mn0);
                s[mt][nt][1] = __expf(s[mt][nt][1] - mn0);
                s[mt][nt][2] = __expf(s[mt][nt][2] - mn1);
                s[mt][nt][3] = __expf(s[mt][nt][3] - mn1);
                sum0 += s[mt][nt][0] + s[mt][nt][1];
                sum1 += s[mt][nt][2] + s[mt][nt][3];
                *(uint2*)&Ps[row * PS_STR + nt * 8 + 2 * tig] =
                    make_uint2(rn_tf32(s[mt][nt][0]), rn_tf32(s[mt][nt][1]));
                *(uint2*)&Ps[(row + 8) * PS_STR + nt * 8 + 2 * tig] =
                    make_uint2(rn_tf32(s[mt][nt][2]), rn_tf32(s[mt][nt][3]));
            }
#pragma unroll
            for (int off = 1; off < 4; off <<= 1) {
                sum0 += __shfl_xor_sync(0xffffffffu, sum0, off, 4);
                sum1 += __shfl_xor_sync(0xffffffffu, sum1, off, 4);
            }
            l[mt][0] = l[mt][0] * c0 + sum0;
            l[mt][1] = l[mt][1] * c1 + sum1;
#pragma unroll
            for (int nt = 0; nt < 8; ++nt) {
                o[mt][nt][0] *= c0; o[mt][nt][1] *= c0;
                o[mt][nt][2] *= c1; o[mt][nt][3] *= c1;
            }
        }
        __syncwarp();   // P rows are warp-private

        // O += P @ V  (V B-frags shared across mt)
#pragma unroll
        for (int kk = 0; kk < 8; ++kk) {
            uint32_t a0[4], a1[4];
            const int r0 = warp * 32 + g;
            a0[0] = Ps[r0 * PS_STR + kk * 8 + tig];
            a0[1] = Ps[(r0 + 8) * PS_STR + kk * 8 + tig];
            a0[2] = Ps[r0 * PS_STR + kk * 8 + tig + 4];
            a0[3] = Ps[(r0 + 8) * PS_STR + kk * 8 + tig + 4];
            a1[0] = Ps[(r0 + 16) * PS_STR + kk * 8 + tig];
            a1[1] = Ps[(r0 + 24) * PS_STR + kk * 8 + tig];
            a1[2] = Ps[(r0 + 16) * PS_STR + kk * 8 + tig + 4];
            a1[3] = Ps[(r0 + 24) * PS_STR + kk * 8 + tig + 4];
#pragma unroll
            for (int nt = 0; nt < 8; ++nt) {
                uint2 bb = *(const uint2*)
                    &Vs[(nt * 8 + g) * VS_STR + kk * 8 + 2 * tig];
                mma_tf32(o[0][nt], a0, bb.x, bb.y);
                mma_tf32(o[1][nt], a1, bb.x, bb.y);
            }
        }
    }

    // Epilogue: normalize, write ctx [B*S, DM] fp32
#pragma unroll
    for (int mt = 0; mt < 2; ++mt) {
        const float inv0 = 1.f / l[mt][0], inv1 = 1.f / l[mt][1];
        const int row0 = qt * 128 + warp * 32 + mt * 16 + g;
#pragma unroll
        for (int nt = 0; nt < 8; ++nt) {
            int col = h * DH + nt * 8 + 2 * tig;
            *(float2*)&g_ctx[(size_t)(b * SEQ + row0) * DM + col] =
                make_float2(o[mt][nt][0] * inv0, o[mt][nt][1] * inv0);
            *(float2*)&g_ctx[(size_t)(b * SEQ + row0 + 8) * DM + col] =
                make_float2(o[mt][nt][2] * inv1, o[mt][nt][3] * inv1);
        }
    }
}

// ---------------------------------------------------------------------------
// Launch
// ---------------------------------------------------------------------------
extern "C" void kernel_launch(void* const* d_in, const int* in_sizes, int n_in,
                              void* d_out, int out_size)
{
    const float* x  = (const float*)d_in[0];
    const float* Wq = (const float*)d_in[1];
    const float* bq = (const float*)d_in[2];
    const float* Wk = (const float*)d_in[3];
    const float* bk = (const float*)d_in[4];
    const float* Wv = (const float*)d_in[5];
    const float* bv = (const float*)d_in[6];
    const float* Wo = (const float*)d_in[7];
    const float* bo = (const float*)d_in[8];
    float* out = (float*)d_out;

    uint32_t *Qp, *Kp, *Vp;
    float *Cp;
    cudaGetSymbolAddress((void**)&Qp, g_Q);
    cudaGetSymbolAddress((void**)&Kp, g_K);
    cudaGetSymbolAddress((void**)&Vp, g_V);
    cudaGetSymbolAddress((void**)&Cp, g_ctx);

    cudaFuncSetAttribute(flash_mma,
                         cudaFuncAttributeMaxDynamicSharedMemorySize, FLASH_SMEM);

    dim3 gg(DM / 128, NTOK / 128);   // (8, 64)
    mma_gemm<<<gg, 256>>>(x, Wq, bq, Qp, 1);
    mma_gemm<<<gg, 256>>>(x, Wk, bk, Kp, 2);
    mma_gemm<<<gg, 256>>>(x, Wv, bv, Vp, 3);

    flash_mma<<<dim3(SEQ / 128, NH, B_SZ), 128, FLASH_SMEM>>>(Qp, Kp, Vp);

    mma_gemm<<<gg, 256>>>(Cp, Wo, bo, out, 0);
}

// round 12
// speedup vs baseline: 4.1411x; 1.2341x over previous
#include <cuda_runtime.h>
#include <cuda_bf16.h>
#include <math.h>
#include <stdint.h>

// Problem constants
#define B_SZ 4
#define SEQ  2048
#define DM   1024
#define NH   16
#define DH   64
#define NTOK (B_SZ * SEQ)   // 8192

// ---------------------------------------------------------------------------
// Scratch (device globals).
// g_Q/g_K: tf32 bits, [B,H,S, p8(dh)]   (Q pre-scaled by 0.125)
// g_V:     tf32 bits, [B,H, S/64, dh, p8(s%64)]
// g_ctx:   tf32 bits  [B*S, DM]   (flash writes rounded; O-GEMM streams raw)
// g_xt:    tf32 bits of x;  g_Wt: tf32 bits of Wq,Wk,Wv,Wo
// ---------------------------------------------------------------------------
__device__ uint32_t g_Q[(size_t)B_SZ * NH * SEQ * DH];
__device__ uint32_t g_K[(size_t)B_SZ * NH * SEQ * DH];
__device__ uint32_t g_V[(size_t)B_SZ * NH * SEQ * DH];
__device__ uint32_t g_ctx[(size_t)NTOK * DM];
__device__ uint32_t g_xt[(size_t)NTOK * DM];
__device__ uint32_t g_Wt[(size_t)4 * DM * DM];

__device__ __forceinline__ int p8(int k) {
    return (k & ~7) + ((k & 3) << 1) + ((k >> 2) & 1);
}
__device__ __forceinline__ uint32_t rn_tf32(float x) {
    uint32_t r;
    asm("cvt.rna.tf32.f32 %0, %1;" : "=r"(r) : "f"(x));
    return r;
}
__device__ __forceinline__ uint32_t smem_u32(const void* p) {
    uint32_t a;
    asm("{ .reg .u64 t; cvta.to.shared.u64 t, %1; cvt.u32.u64 %0, t; }"
        : "=r"(a) : "l"(p));
    return a;
}
__device__ __forceinline__ void mma_tf32(float* c, const uint32_t* a,
                                         uint32_t b0, uint32_t b1) {
    asm volatile(
        "mma.sync.aligned.m16n8k8.row.col.f32.tf32.tf32.f32 "
        "{%0,%1,%2,%3}, {%4,%5,%6,%7}, {%8,%9}, {%0,%1,%2,%3};"
        : "+f"(c[0]), "+f"(c[1]), "+f"(c[2]), "+f"(c[3])
        : "r"(a[0]), "r"(a[1]), "r"(a[2]), "r"(a[3]), "r"(b0), "r"(b1));
}

#define CP16(dst32, src) \
    asm volatile("cp.async.cg.shared.global [%0], [%1], 16;" \
                 :: "r"(dst32), "l"(src) : "memory")
#define CP_COMMIT() asm volatile("cp.async.commit_group;" ::: "memory")
#define CP_WAIT0()  asm volatile("cp.async.wait_group 0;" ::: "memory")

// ---------------------------------------------------------------------------
// Prep: fp32 -> tf32 bits (rna), vectorized. n = elems, grid*256*4 == n.
// ---------------------------------------------------------------------------
__global__ __launch_bounds__(256) void prep_tf32(
    const float* __restrict__ in, uint32_t* __restrict__ out)
{
    size_t i = ((size_t)blockIdx.x * 256 + threadIdx.x) * 4;
    float4 v = *(const float4*)&in[i];
    *(uint4*)&out[i] = make_uint4(rn_tf32(v.x), rn_tf32(v.y),
                                  rn_tf32(v.z), rn_tf32(v.w));
}

// ---------------------------------------------------------------------------
// TF32 mma GEMM body: out[M,N] = A@W + bias, A/W pre-converted tf32 bits.
// Double-buffered cp.async pipeline, ONE barrier per 32-k chunk.
// mode 0: fp32 out [M,DM] | 1: Q (x0.125, p8) | 2: K (p8) | 3: V (transposed)
// ---------------------------------------------------------------------------
#define AS_U 4608            // 128*36
#define BS_U 4352            // 32*136
#define GEMM_SMEM ((2 * AS_U + 2 * BS_U) * 4)    // 71680 B

__device__ __forceinline__ void gemm_body(
    const uint32_t* __restrict__ A, const uint32_t* __restrict__ W,
    const float* __restrict__ bias, void* __restrict__ outv, int mode)
{
    extern __shared__ uint32_t gsm[];
    const int tid  = threadIdx.x;
    const int warp = tid >> 5, lane = tid & 31;
    const int wm = warp >> 2, wn = warp & 3;
    const int g  = lane >> 2, tig = lane & 3;
    const int m0 = blockIdx.y * 128;
    const int n0 = blockIdx.x * 128;
    const uint32_t sb = smem_u32(gsm);

    float acc[4][4][4];
#pragma unroll
    for (int mt = 0; mt < 4; ++mt)
#pragma unroll
        for (int nt = 0; nt < 4; ++nt)
#pragma unroll
            for (int r = 0; r < 4; ++r) acc[mt][nt][r] = 0.f;

    auto issue_chunk = [&](int c) {
        const int k0 = c * 32;
        const uint32_t ab = sb + ((c & 1) * AS_U) * 4;
        const uint32_t bb = sb + (2 * AS_U + (c & 1) * BS_U) * 4;
#pragma unroll
        for (int i = 0; i < 4; ++i) {
            int it = i * 256 + tid;
            int r = it >> 3, c4 = it & 7;
            CP16(ab + (r * 36 + c4 * 4) * 4,
                 &A[(size_t)(m0 + r) * DM + k0 + c4 * 4]);
        }
#pragma unroll
        for (int i = 0; i < 4; ++i) {
            int it = i * 256 + tid;
            int k = it >> 5, n4 = it & 31;
            CP16(bb + (k * 136 + n4 * 4) * 4,
                 &W[(size_t)(k0 + k) * DM + n0 + n4 * 4]);
        }
    };

    issue_chunk(0);
    CP_COMMIT();

    for (int c = 0; c < 32; ++c) {
        CP_WAIT0();
        __syncthreads();
        if (c + 1 < 32) { issue_chunk(c + 1); CP_COMMIT(); }

        const uint32_t* As = gsm + (c & 1) * AS_U;
        const uint32_t* Bs = gsm + 2 * AS_U + (c & 1) * BS_U;
#pragma unroll
        for (int kk = 0; kk < 32; kk += 8) {
            uint32_t a[4][4], b[4][2];
#pragma unroll
            for (int mt = 0; mt < 4; ++mt) {
                int row = wm * 64 + mt * 16;
                a[mt][0] = As[(row + g    ) * 36 + kk + tig];
                a[mt][1] = As[(row + g + 8) * 36 + kk + tig];
                a[mt][2] = As[(row + g    ) * 36 + kk + tig + 4];
                a[mt][3] = As[(row + g + 8) * 36 + kk + tig + 4];
            }
#pragma unroll
            for (int nt = 0; nt < 4; ++nt) {
                int coln = wn * 32 + nt * 8 + g;
                b[nt][0] = Bs[(kk + tig    ) * 136 + coln];
                b[nt][1] = Bs[(kk + tig + 4) * 136 + coln];
            }
#pragma unroll
            for (int mt = 0; mt < 4; ++mt)
#pragma unroll
                for (int nt = 0; nt < 4; ++nt)
                    mma_tf32(acc[mt][nt], a[mt], b[nt][0], b[nt][1]);
        }
    }

#pragma unroll
    for (int mt = 0; mt < 4; ++mt) {
#pragma unroll
        for (int nt = 0; nt < 4; ++nt) {
            int col  = n0 + wn * 32 + nt * 8 + 2 * tig;
            float2 bv = *(const float2*)&bias[col];
#pragma unroll
            for (int hh = 0; hh < 2; ++hh) {
                int t = m0 + wm * 64 + mt * 16 + g + hh * 8;
                float ox = acc[mt][nt][hh * 2 + 0] + bv.x;
                float oy = acc[mt][nt][hh * 2 + 1] + bv.y;
                if (mode == 0) {
                    *(float2*)&((float*)outv)[(size_t)t * DM + col] =
                        make_float2(ox, oy);
                } else {
                    int bidx = t >> 11;
                    int srow = t & (SEQ - 1);
                    int head = col >> 6;
                    int dh   = col & (DH - 1);
                    uint32_t* dst = (uint32_t*)outv;
                    size_t hb = (size_t)(bidx * NH + head) * SEQ * DH;
                    if (mode != 3) {
                        float sc = (mode == 1) ? 0.125f : 1.0f;
                        dst[hb + (size_t)srow * DH + p8(dh)] =
                            rn_tf32(ox * sc);
                        dst[hb + (size_t)srow * DH + p8(dh + 1)] =
                            rn_tf32(oy * sc);
                    } else {
                        size_t base = hb + (size_t)(srow >> 6) * (DH * 64)
                                      + p8(srow & 63);
                        dst[base + (size_t)dh * 64]       = rn_tf32(ox);
                        dst[base + (size_t)(dh + 1) * 64] = rn_tf32(oy);
                    }
                }
            }
        }
    }
}

__global__ __launch_bounds__(256) void qkv_gemm(
    const uint32_t* __restrict__ xt, const uint32_t* __restrict__ Wt,
    const float* __restrict__ bq, const float* __restrict__ bk,
    const float* __restrict__ bv,
    uint32_t* __restrict__ Qo, uint32_t* __restrict__ Ko,
    uint32_t* __restrict__ Vo)
{
    const int z = blockIdx.z;
    const uint32_t* W = Wt + (size_t)z * DM * DM;
    const float* bias = (z == 0) ? bq : (z == 1) ? bk : bv;
    void* out = (z == 0) ? (void*)Qo : (z == 1) ? (void*)Ko : (void*)Vo;
    gemm_body(xt, W, bias, out, z + 1);
}

__global__ __launch_bounds__(256) void o_gemm(
    const uint32_t* __restrict__ ctx, const uint32_t* __restrict__ Wt,
    const float* __restrict__ bo, float* __restrict__ out)
{
    gemm_body(ctx, Wt + (size_t)3 * DM * DM, bo, out, 0);
}

// ---------------------------------------------------------------------------
// TF32 mma flash attention v3: double-buffered cp.async K/V, one barrier/kb.
// CTA 128 thr (4 warps) x 128 q-rows; warp = 32 rows (mt=2); B-frags reused.
//   Ks/Vs stride 72, Ps stride 76 (bank patterns validated R10/R11).
// ---------------------------------------------------------------------------
#define KS_STR 72
#define VS_STR 72
#define PS_STR 76
#define PS_U32 (128 * PS_STR)          // 9728
#define KS_U32 (64 * KS_STR)           // 4608
#define KV_U32 (2 * KS_U32)            // 9216 per buffer (K + V)
#define FLASH_SMEM ((PS_U32 + 2 * KV_U32) * 4)   // 112640 B

__global__ __launch_bounds__(128, 2) void flash_mma(
    const uint32_t* __restrict__ Q, const uint32_t* __restrict__ K,
    const uint32_t* __restrict__ V)
{
    extern __shared__ uint32_t sm4[];
    uint32_t* Ps = sm4;
    const uint32_t sb = smem_u32(sm4);

    const int tid  = threadIdx.x;
    const int warp = tid >> 5, lane = tid & 31;
    const int g    = lane >> 2;
    const int tig  = lane & 3;
    const int qt = blockIdx.x;
    const int h  = blockIdx.y;
    const int b  = blockIdx.z;

    const size_t head_off = (size_t)(b * NH + h) * SEQ * DH;
    const uint32_t* Qg = Q + head_off + (size_t)qt * 128 * DH;
    const uint32_t* Kg = K + head_off;
    const uint32_t* Vg = V + head_off;

    auto issue_kv = [&](int kb) {
        const uint32_t kbase = sb + (PS_U32 + (kb & 1) * KV_U32) * 4;
        const uint32_t vbase = kbase + KS_U32 * 4;
#pragma unroll
        for (int i = 0; i < 8; ++i) {
            int it = i * 128 + tid;
            int r = it >> 4, c4 = (it & 15) * 4;
            CP16(kbase + (r * KS_STR + c4) * 4,
                 &Kg[(size_t)(kb * 64 + r) * DH + c4]);
            CP16(vbase + (r * VS_STR + c4) * 4,
                 &Vg[(size_t)kb * (DH * 64) + r * 64 + c4]);
        }
    };

    issue_kv(0);
    CP_COMMIT();

    // Q fragments straight from gmem (paired layout -> LDG.64); overlaps copy
    uint32_t qf[2][8][4];
#pragma unroll
    for (int mt = 0; mt < 2; ++mt) {
        const int row = warp * 32 + mt * 16 + g;
#pragma unroll
        for (int kk = 0; kk < 8; ++kk) {
            uint2 q02 = *(const uint2*)&Qg[(size_t)row * DH + kk * 8 + 2 * tig];
            uint2 q13 = *(const uint2*)&Qg[(size_t)(row + 8) * DH + kk * 8 + 2 * tig];
            qf[mt][kk][0] = q02.x; qf[mt][kk][2] = q02.y;
            qf[mt][kk][1] = q13.x; qf[mt][kk][3] = q13.y;
        }
    }

    float o[2][8][4];
#pragma unroll
    for (int mt = 0; mt < 2; ++mt)
#pragma unroll
        for (int nt = 0; nt < 8; ++nt)
#pragma unroll
            for (int r = 0; r < 4; ++r) o[mt][nt][r] = 0.f;
    float m[2][2], l[2][2];
#pragma unroll
    for (int mt = 0; mt < 2; ++mt) {
        m[mt][0] = m[mt][1] = -1e30f;
        l[mt][0] = l[mt][1] = 0.f;
    }

    for (int kb = 0; kb < SEQ / 64; ++kb) {
        CP_WAIT0();
        __syncthreads();   // buf[kb&1] visible; all warps done with buf[(kb-1)&1]
        if (kb + 1 < SEQ / 64) { issue_kv(kb + 1); CP_COMMIT(); }

        const uint32_t* Ks = sm4 + PS_U32 + (kb & 1) * KV_U32;
        const uint32_t* Vs = Ks + KS_U32;

        // S = Q @ K^T : 32 rows x 64 cols per warp, B-frags shared across mt
        float s[2][8][4];
#pragma unroll
        for (int mt = 0; mt < 2; ++mt)
#pragma unroll
            for (int nt = 0; nt < 8; ++nt)
#pragma unroll
                for (int r = 0; r < 4; ++r) s[mt][nt][r] = 0.f;
#pragma unroll
        for (int kk = 0; kk < 8; ++kk) {
#pragma unroll
            for (int nt = 0; nt < 8; ++nt) {
                uint2 bb = *(const uint2*)
                    &Ks[(nt * 8 + g) * KS_STR + kk * 8 + 2 * tig];
                mma_tf32(s[0][nt], qf[0][kk], bb.x, bb.y);
                mma_tf32(s[1][nt], qf[1][kk], bb.x, bb.y);
            }
        }

        // Online softmax per m-tile (rows g and g+8; reduce over 4-lane quad)
#pragma unroll
        for (int mt = 0; mt < 2; ++mt) {
            float mx0 = -1e30f, mx1 = -1e30f;
#pragma unroll
            for (int nt = 0; nt < 8; ++nt) {
                mx0 = fmaxf(mx0, fmaxf(s[mt][nt][0], s[mt][nt][1]));
                mx1 = fmaxf(mx1, fmaxf(s[mt][nt][2], s[mt][nt][3]));
            }
#pragma unroll
            for (int off = 1; off < 4; off <<= 1) {
                mx0 = fmaxf(mx0, __shfl_xor_sync(0xffffffffu, mx0, off, 4));
                mx1 = fmaxf(mx1, __shfl_xor_sync(0xffffffffu, mx1, off, 4));
            }
            float mn0 = fmaxf(m[mt][0], mx0), mn1 = fmaxf(m[mt][1], mx1);
            float c0 = __expf(m[mt][0] - mn0), c1 = __expf(m[mt][1] - mn1);
            m[mt][0] = mn0; m[mt][1] = mn1;

            float sum0 = 0.f, sum1 = 0.f;
            const int row = warp * 32 + mt * 16 + g;
#pragma unroll
            for (int nt = 0; nt < 8; ++nt) {
                s[mt][nt][0] = __expf(s[mt][nt][0] - mn0);
                s[mt][nt][1] = __expf(s[mt][nt][1] - mn0);
                s[mt][nt][2] = __expf(s[mt][nt][2] - mn1);
                s[mt][nt][3] = __expf(s[mt][nt][3] - mn1);
                sum0 += s[mt][nt][0] + s[mt][nt][1];
                sum1 += s[mt][nt][2] + s[mt][nt][3];
                *(uint2*)&Ps[row * PS_STR + nt * 8 + 2 * tig] =
                    make_uint2(rn_tf32(s[mt][nt][0]), rn_tf32(s[mt][nt][1]));
                *(uint2*)&Ps[(row + 8) * PS_STR + nt * 8 + 2 * tig] =
                    make_uint2(rn_tf32(s[mt][nt][2]), rn_tf32(s[mt][nt][3]));
            }
#pragma unroll
            for (int off = 1; off < 4; off <<= 1) {
                sum0 += __shfl_xor_sync(0xffffffffu, sum0, off, 4);
                sum1 += __shfl_xor_sync(0xffffffffu, sum1, off, 4);
            }
            l[mt][0] = l[mt][0] * c0 + sum0;
            l[mt][1] = l[mt][1] * c1 + sum1;
#pragma unroll
            for (int nt = 0; nt < 8; ++nt) {
                o[mt][nt][0] *= c0; o[mt][nt][1] *= c0;
                o[mt][nt][2] *= c1; o[mt][nt][3] *= c1;
            }
        }
        __syncwarp();   // P rows are warp-private

        // O += P @ V  (V B-frags shared across mt)
#pragma unroll
        for (int kk = 0; kk < 8; ++kk) {
            uint32_t a0[4], a1[4];
            const int r0 = warp * 32 + g;
            a0[0] = Ps[r0 * PS_STR + kk * 8 + tig];
            a0[1] = Ps[(r0 + 8) * PS_STR + kk * 8 + tig];
            a0[2] = Ps[r0 * PS_STR + kk * 8 + tig + 4];
            a0[3] = Ps[(r0 + 8) * PS_STR + kk * 8 + tig + 4];
            a1[0] = Ps[(r0 + 16) * PS_STR + kk * 8 + tig];
            a1[1] = Ps[(r0 + 24) * PS_STR + kk * 8 + tig];
            a1[2] = Ps[(r0 + 16) * PS_STR + kk * 8 + tig + 4];
            a1[3] = Ps[(r0 + 24) * PS_STR + kk * 8 + tig + 4];
#pragma unroll
            for (int nt = 0; nt < 8; ++nt) {
                uint2 bb = *(const uint2*)
                    &Vs[(nt * 8 + g) * VS_STR + kk * 8 + 2 * tig];
                mma_tf32(o[0][nt], a0, bb.x, bb.y);
                mma_tf32(o[1][nt], a1, bb.x, bb.y);
            }
        }
    }

    // Epilogue: normalize, write ctx as tf32 bits (O-GEMM streams it raw)
#pragma unroll
    for (int mt = 0; mt < 2; ++mt) {
        const float inv0 = 1.f / l[mt][0], inv1 = 1.f / l[mt][1];
        const int row0 = qt * 128 + warp * 32 + mt * 16 + g;
#pragma unroll
        for (int nt = 0; nt < 8; ++nt) {
            int col = h * DH + nt * 8 + 2 * tig;
            *(uint2*)&g_ctx[(size_t)(b * SEQ + row0) * DM + col] =
                make_uint2(rn_tf32(o[mt][nt][0] * inv0),
                           rn_tf32(o[mt][nt][1] * inv0));
            *(uint2*)&g_ctx[(size_t)(b * SEQ + row0 + 8) * DM + col] =
                make_uint2(rn_tf32(o[mt][nt][2] * inv1),
                           rn_tf32(o[mt][nt][3] * inv1));
        }
    }
}

// ---------------------------------------------------------------------------
// Launch
// ---------------------------------------------------------------------------
extern "C" void kernel_launch(void* const* d_in, const int* in_sizes, int n_in,
                              void* d_out, int out_size)
{
    const float* x  = (const float*)d_in[0];
    const float* Wq = (const float*)d_in[1];
    const float* bq = (const float*)d_in[2];
    const float* Wk = (const float*)d_in[3];
    const float* bk = (const float*)d_in[4];
    const float* Wv = (const float*)d_in[5];
    const float* bv = (const float*)d_in[6];
    const float* Wo = (const float*)d_in[7];
    const float* bo = (const float*)d_in[8];
    float* out = (float*)d_out;

    uint32_t *Qp, *Kp, *Vp, *Cp, *Xp, *Wp;
    cudaGetSymbolAddress((void**)&Qp, g_Q);
    cudaGetSymbolAddress((void**)&Kp, g_K);
    cudaGetSymbolAddress((void**)&Vp, g_V);
    cudaGetSymbolAddress((void**)&Cp, g_ctx);
    cudaGetSymbolAddress((void**)&Xp, g_xt);
    cudaGetSymbolAddress((void**)&Wp, g_Wt);

    cudaFuncSetAttribute(flash_mma,
                         cudaFuncAttributeMaxDynamicSharedMemorySize, FLASH_SMEM);
    cudaFuncSetAttribute(qkv_gemm,
                         cudaFuncAttributeMaxDynamicSharedMemorySize, GEMM_SMEM);
    cudaFuncSetAttribute(o_gemm,
                         cudaFuncAttributeMaxDynamicSharedMemorySize, GEMM_SMEM);

    // Prep: x and W -> tf32 bits (rna) once
    prep_tf32<<<(NTOK * DM) / 1024, 256>>>(x, Xp);
    prep_tf32<<<(DM * DM) / 1024, 256>>>(Wq, Wp + 0 * (size_t)DM * DM);
    prep_tf32<<<(DM * DM) / 1024, 256>>>(Wk, Wp + 1 * (size_t)DM * DM);
    prep_tf32<<<(DM * DM) / 1024, 256>>>(Wv, Wp + 2 * (size_t)DM * DM);
    prep_tf32<<<(DM * DM) / 1024, 256>>>(Wo, Wp + 3 * (size_t)DM * DM);

    qkv_gemm<<<dim3(DM / 128, NTOK / 128, 3), 256, GEMM_SMEM>>>(
        Xp, Wp, bq, bk, bv, Qp, Kp, Vp);

    flash_mma<<<dim3(SEQ / 128, NH, B_SZ), 128, FLASH_SMEM>>>(Qp, Kp, Vp);

    o_gemm<<<dim3(DM / 128, NTOK / 128), 256, GEMM_SMEM>>>(Cp, Wp, bo, out);
}